// round 6
// baseline (speedup 1.0000x reference)
#include <cuda_runtime.h>
#include <cuda_fp16.h>

#define NN 100000
#define NE 1600000
#define FIN 128
#define HID 64
#define SCAN_NBLK 98     // ceil(NN/1024)
#define CSR_B 148
#define CSR_T 1024

typedef unsigned int uint32;

// ---------------- scratch (device globals; no allocation allowed) ----------------
__device__ __align__(256) __half2 g_h0h[(size_t)NN * 32];  // fp16 agg input (64 feats/node)
__device__ __align__(256) __half2 g_h1h[(size_t)NN * 32];  // conv1 output (fp16)
__device__ __align__(256) float  g_y [(size_t)NN * 16];    // per-node edge-head partials
__device__ __align__(256) float  g_dinv[NN];
__device__ __align__(256) int    g_deg[NN];
__device__ __align__(256) int    g_cursor[NN];
__device__ __align__(256) int    g_rowptr[NN + 1];
__device__ __align__(256) int2   g_srcw[NE];               // {src, bits(dinv[src])}
__device__ __align__(256) int    g_bsums[128];
__device__ int g_barc[8];   // one-shot barrier counters (zero-init; reset by k_agg<false>)

// ---------------- software grid barrier ----------------
__device__ __forceinline__ void gbar(int j) {
    __syncthreads();
    if (threadIdx.x == 0) {
        __threadfence();
        atomicAdd(&g_barc[j], 1);
        volatile int* p = &g_barc[j];
        while (*p < CSR_B) { }
        __threadfence();
    }
    __syncthreads();
}

// ---------------- fused CSR build ----------------
__global__ __launch_bounds__(CSR_T) void k_csr(const int* __restrict__ row,
                                               const int* __restrict__ col) {
    const int tid = threadIdx.x, bid = blockIdx.x;
    const int gt = bid * CSR_T + tid;
    const int gstride = CSR_B * CSR_T;

    for (int i = gt; i < NN; i += gstride) g_deg[i] = 0;
    gbar(0);

    for (int e = gt; e < NE; e += gstride) atomicAdd(&g_deg[col[e]], 1);
    gbar(1);

    int excl = 0;
    int valid = 0;
    if (bid < SCAN_NBLK) {
        int i = bid * CSR_T + tid;
        valid = (i < NN);
        int v = valid ? __ldcg(&g_deg[i]) : 0;
        if (valid) g_dinv[i] = rsqrtf((float)v + 1.0f);   // +1 self-loop
        int lane = tid & 31, wid = tid >> 5;
        int x = v;
        #pragma unroll
        for (int d = 1; d < 32; d <<= 1) {
            int y = __shfl_up_sync(0xffffffffu, x, d);
            if (lane >= d) x += y;
        }
        __shared__ int wsum[32];
        if (lane == 31) wsum[wid] = x;
        __syncthreads();
        if (wid == 0) {
            int s = wsum[lane];
            int sx = s;
            #pragma unroll
            for (int d = 1; d < 32; d <<= 1) {
                int y = __shfl_up_sync(0xffffffffu, sx, d);
                if (lane >= d) sx += y;
            }
            wsum[lane] = sx - s;
        }
        __syncthreads();
        int incl = x + wsum[wid];
        excl = incl - v;
        if (tid == 1023) g_bsums[bid] = incl;
    }
    gbar(2);

    {
        __shared__ int ws[4];
        int v = 0, incl = 0;
        if (bid == 0) {
            if (tid < 128) {
                v = (tid < SCAN_NBLK) ? __ldcg(&g_bsums[tid]) : 0;
                int lane = tid & 31, wid = tid >> 5;
                int x = v;
                #pragma unroll
                for (int d = 1; d < 32; d <<= 1) {
                    int y = __shfl_up_sync(0xffffffffu, x, d);
                    if (lane >= d) x += y;
                }
                if (lane == 31) ws[wid] = x;
                incl = x;
            }
            __syncthreads();
            if (tid < 128) {
                int wid = tid >> 5;
                int off = 0;
                for (int w = 0; w < wid; w++) off += ws[w];
                incl += off;
                if (tid < SCAN_NBLK) g_bsums[tid] = incl - v;
            }
        }
    }
    gbar(3);

    if (bid < SCAN_NBLK && valid) {
        int i = bid * CSR_T + tid;
        int rp = excl + __ldcg(&g_bsums[bid]);
        g_rowptr[i] = rp;
        g_cursor[i] = rp;
    }
    if (bid == 0 && tid == 0) g_rowptr[NN] = NE;
    gbar(4);

    for (int e = gt; e < NE; e += gstride) {
        int c = col[e];
        int r = row[e];
        int p = atomicAdd(&g_cursor[c], 1);
        float dv = __ldcg(&g_dinv[r]);
        g_srcw[p] = make_int2(r, __float_as_int(dv));
    }
}

// ---------------- tensor-core GEMM: g_h0h[n,64](fp16) = A[n,K] @ W[K,64] ----------------
// mma.sync.m16n8k16 (fp16 in, fp32 accum). 512 thr = 16 warps x 16 rows = 256 rows/block.
__device__ __forceinline__ void mma16816(float d[4], uint32 a0, uint32 a1, uint32 a2,
                                         uint32 a3, uint32 b0, uint32 b1) {
    asm volatile(
        "mma.sync.aligned.m16n8k16.row.col.f32.f16.f16.f32 "
        "{%0,%1,%2,%3}, {%4,%5,%6,%7}, {%8,%9}, {%0,%1,%2,%3};"
        : "+f"(d[0]), "+f"(d[1]), "+f"(d[2]), "+f"(d[3])
        : "r"(a0), "r"(a1), "r"(a2), "r"(a3), "r"(b0), "r"(b1));
}

// A_HALF=false: A = Af (fp32 gmem input).  A_HALF=true: A = g_h1h (device symbol,
// selected INSIDE device code only).
template <int K, bool A_HALF>
__global__ __launch_bounds__(512) void k_gemm_mma(const float* __restrict__ Af,
                                                  const float* __restrict__ W) {
    __shared__ __half Wt[64][K + 8];    // W transposed [n][k]

    for (int i = threadIdx.x; i < K * 64; i += 512) {
        int k = i >> 6, n = i & 63;
        Wt[n][k] = __float2half(W[i]);
    }
    __syncthreads();

    const __half* Ah = reinterpret_cast<const __half*>(g_h1h);

    const int warp = threadIdx.x >> 5, lane = threadIdx.x & 31;
    const int gr = lane >> 2;           // 0..7
    const int kc = (lane & 3) * 2;      // 0,2,4,6
    const int r0 = blockIdx.x * 256 + warp * 16 + gr;
    const int r1 = r0 + 8;
    const bool v0 = r0 < NN, v1 = r1 < NN;

    float d[8][4];
    #pragma unroll
    for (int nt = 0; nt < 8; nt++)
        #pragma unroll
        for (int t = 0; t < 4; t++) d[nt][t] = 0.f;

    #pragma unroll
    for (int q = 0; q < K / 16; q++) {
        int k0 = q * 16 + kc;
        uint32 a0 = 0, a1 = 0, a2 = 0, a3 = 0;
        if (A_HALF) {
            if (v0) {
                a0 = *reinterpret_cast<const uint32*>(Ah + (size_t)r0 * K + k0);
                a2 = *reinterpret_cast<const uint32*>(Ah + (size_t)r0 * K + k0 + 8);
            }
            if (v1) {
                a1 = *reinterpret_cast<const uint32*>(Ah + (size_t)r1 * K + k0);
                a3 = *reinterpret_cast<const uint32*>(Ah + (size_t)r1 * K + k0 + 8);
            }
        } else {
            if (v0) {
                float2 f0 = *reinterpret_cast<const float2*>(Af + (size_t)r0 * K + k0);
                float2 f2 = *reinterpret_cast<const float2*>(Af + (size_t)r0 * K + k0 + 8);
                __half2 h0 = __float22half2_rn(f0), h2 = __float22half2_rn(f2);
                a0 = *reinterpret_cast<uint32*>(&h0);
                a2 = *reinterpret_cast<uint32*>(&h2);
            }
            if (v1) {
                float2 f1 = *reinterpret_cast<const float2*>(Af + (size_t)r1 * K + k0);
                float2 f3 = *reinterpret_cast<const float2*>(Af + (size_t)r1 * K + k0 + 8);
                __half2 h1 = __float22half2_rn(f1), h3 = __float22half2_rn(f3);
                a1 = *reinterpret_cast<uint32*>(&h1);
                a3 = *reinterpret_cast<uint32*>(&h3);
            }
        }
        #pragma unroll
        for (int nt = 0; nt < 8; nt++) {
            int n = nt * 8 + gr;
            uint32 b0 = *reinterpret_cast<const uint32*>(&Wt[n][k0]);
            uint32 b1 = *reinterpret_cast<const uint32*>(&Wt[n][k0 + 8]);
            mma16816(d[nt], a0, a1, a2, a3, b0, b1);
        }
    }

    // epilogue: direct half2 fragment stores (write volume tiny; keeps smem small)
    __half* outp = reinterpret_cast<__half*>(g_h0h);
    #pragma unroll
    for (int nt = 0; nt < 8; nt++) {
        int c = nt * 8 + kc;
        if (v0) *reinterpret_cast<__half2*>(outp + (size_t)r0 * 64 + c) =
            __floats2half2_rn(d[nt][0], d[nt][1]);
        if (v1) *reinterpret_cast<__half2*>(outp + (size_t)r1 * 64 + c) =
            __floats2half2_rn(d[nt][2], d[nt][3]);
    }
}

// ---------------- GCN aggregate (+optional fused edge-head GEMV) ----------------
template <bool FUSE_HEAD>
__global__ __launch_bounds__(256) void k_agg(const float* __restrict__ bias,
                                             const float* __restrict__ Wl,
                                             const float* __restrict__ bl) {
    // agg1 (FUSE_HEAD=false) runs strictly after k_csr joins -> safe place to
    // reset the CSR grid-barrier counters for the next graph replay.
    if (!FUSE_HEAD && blockIdx.x == 0 && threadIdx.x == 0) {
        #pragma unroll
        for (int j = 0; j < 8; j++) g_barc[j] = 0;
    }
    __shared__ float Wls[16 * 68];
    __shared__ float hs[8][64];
    __shared__ float blc[8];
    if (FUSE_HEAD) {
        for (int i = threadIdx.x; i < 16 * 64; i += 256) {
            int o = i & 15, k = i >> 4;
            int sel = o >> 3, oo = o & 7;
            Wls[o * 68 + k] = Wl[(sel * 64 + k) * 8 + oo];
        }
        if (threadIdx.x < 8) blc[threadIdx.x] = bl[threadIdx.x];
        __syncthreads();
    }

    int gw = (blockIdx.x * 256 + threadIdx.x) >> 5;   // grid exact: 12500 blocks
    int lane = threadIdx.x & 31;
    int w = threadIdx.x >> 5;
    float di = g_dinv[gw];
    int beg = g_rowptr[gw], end = g_rowptr[gw + 1];

    const __half2* hin = g_h0h;
    float2 hself = __half22float2(hin[(size_t)gw * 32 + lane]);
    float sw = di * di;
    float ax = sw * hself.x, ay = sw * hself.y;

    int e = beg;
    for (; e + 4 <= end; e += 4) {
        int2 p0 = __ldg(&g_srcw[e]);
        int2 p1 = __ldg(&g_srcw[e + 1]);
        int2 p2 = __ldg(&g_srcw[e + 2]);
        int2 p3 = __ldg(&g_srcw[e + 3]);
        float w0 = di * __int_as_float(p0.y);
        float w1 = di * __int_as_float(p1.y);
        float w2 = di * __int_as_float(p2.y);
        float w3 = di * __int_as_float(p3.y);
        float2 v0 = __half22float2(__ldg(&hin[(size_t)p0.x * 32 + lane]));
        float2 v1 = __half22float2(__ldg(&hin[(size_t)p1.x * 32 + lane]));
        float2 v2 = __half22float2(__ldg(&hin[(size_t)p2.x * 32 + lane]));
        float2 v3 = __half22float2(__ldg(&hin[(size_t)p3.x * 32 + lane]));
        ax += w0 * v0.x + w1 * v1.x + w2 * v2.x + w3 * v3.x;
        ay += w0 * v0.y + w1 * v1.y + w2 * v2.y + w3 * v3.y;
    }
    for (; e < end; e++) {
        int2 pp = __ldg(&g_srcw[e]);
        float wv = di * __int_as_float(pp.y);
        float2 v = __half22float2(__ldg(&hin[(size_t)pp.x * 32 + lane]));
        ax += wv * v.x;
        ay += wv * v.y;
    }
    float2 b = reinterpret_cast<const float2*>(bias)[lane];
    float rx = fmaxf(ax + b.x, 0.f);
    float ry = fmaxf(ay + b.y, 0.f);

    if (!FUSE_HEAD) {
        g_h1h[(size_t)gw * 32 + lane] = __floats2half2_rn(rx, ry);
    } else {
        hs[w][2 * lane + 0] = rx;
        hs[w][2 * lane + 1] = ry;
        __syncwarp();
        if (lane < 16) {
            float acc = (lane < 8) ? blc[lane] : 0.f;
            const float4* h4 = reinterpret_cast<const float4*>(hs[w]);
            const float4* w4 = reinterpret_cast<const float4*>(Wls + lane * 68);
            #pragma unroll
            for (int k4 = 0; k4 < 16; k4++) {
                float4 hv = h4[k4];
                float4 wv = w4[k4];
                acc += hv.x * wv.x + hv.y * wv.y + hv.z * wv.z + hv.w * wv.w;
            }
            g_y[(size_t)gw * 16 + lane] = acc;
        }
        __syncwarp();
    }
}

// ---------------- edge phase: out[e] = y[row][0:8] + y[col][8:16] ----------------
__global__ void k_edge(const int* __restrict__ row, const int* __restrict__ col,
                       float* __restrict__ out) {
    int idx = blockIdx.x * 256 + threadIdx.x;
    if (idx >= NE * 2) return;
    int e = idx >> 1, c = idx & 1;
    int r = row[e], cl = col[e];
    const float4* y4 = reinterpret_cast<const float4*>(g_y);
    float4 a = y4[(size_t)r * 4 + c];
    float4 b = y4[(size_t)cl * 4 + 2 + c];
    float4 o;
    o.x = a.x + b.x; o.y = a.y + b.y; o.z = a.z + b.z; o.w = a.w + b.w;
    reinterpret_cast<float4*>(out)[idx] = o;
}

// ---------------- launch ----------------
extern "C" void kernel_launch(void* const* d_in, const int* in_sizes, int n_in,
                              void* d_out, int out_size) {
    const float* x  = (const float*)d_in[0];
    const int*   ei = (const int*)  d_in[1];
    const float* W1 = (const float*)d_in[2];
    const float* b1 = (const float*)d_in[3];
    const float* W2 = (const float*)d_in[4];
    const float* b2 = (const float*)d_in[5];
    const float* Wl = (const float*)d_in[6];
    const float* bl = (const float*)d_in[7];
    float* out = (float*)d_out;

    const int* row = ei;        // edge_index[0]
    const int* col = ei + NE;   // edge_index[1]

    const int GEMM_G = (NN + 255) / 256;   // 391 blocks (256 rows each)

    // fork: GEMM1 (independent of CSR) runs on a side stream, overlapping k_csr
    cudaStream_t s2;
    cudaStreamCreateWithFlags(&s2, cudaStreamNonBlocking);
    cudaEvent_t evF, evJ;
    cudaEventCreateWithFlags(&evF, cudaEventDisableTiming);
    cudaEventCreateWithFlags(&evJ, cudaEventDisableTiming);

    cudaEventRecord(evF, 0);
    cudaStreamWaitEvent(s2, evF, 0);
    k_gemm_mma<FIN, false><<<GEMM_G, 512, 0, s2>>>(x, W1);   // conv1 GEMM
    cudaEventRecord(evJ, s2);

    k_csr<<<CSR_B, CSR_T>>>(row, col);                       // CSR build (main stream)
    cudaStreamWaitEvent(0, evJ, 0);                          // join

    // conv1 agg: h1h = fp16(relu(agg(h0h)+b1))   (also resets g_barc)
    k_agg<false><<<(NN * 32) / 256, 256>>>(b1, Wl, bl);

    // conv2 + fused edge head
    k_gemm_mma<HID, true><<<GEMM_G, 512>>>(nullptr, W2);
    k_agg<true><<<(NN * 32) / 256, 256>>>(b2, Wl, bl);

    // per-edge sum
    k_edge<<<(NE * 2 + 255) / 256, 256>>>(row, col, out);

    cudaStreamDestroy(s2);
    cudaEventDestroy(evF);
    cudaEventDestroy(evJ);
}

// round 7
// speedup vs baseline: 1.1063x; 1.1063x over previous
#include <cuda_runtime.h>
#include <cuda_fp16.h>

#define NN 100000
#define NE 1600000
#define FIN 128
#define HID 64
#define SCAN_NBLK 98     // ceil(NN/1024)
#define CSR_B 148
#define CSR_T 1024

typedef unsigned int uint32;

// ---------------- scratch (device globals; no allocation allowed) ----------------
__device__ __align__(256) __half2 g_h0h[(size_t)NN * 32];  // premultiplied gemm out (fp16)
__device__ __align__(256) __half2 g_h1h[(size_t)NN * 32];  // conv1 hidden (fp16, unscaled)
__device__ __align__(256) float  g_y [(size_t)NN * 16];    // per-node edge-head partials
__device__ __align__(256) float  g_dinv[NN];
__device__ __align__(256) int    g_deg[NN];
__device__ __align__(256) int    g_cursor[NN];
__device__ __align__(256) int    g_rowptr[NN + 1];
__device__ __align__(256) int    g_src[NE];                // CSR payload: source node only
__device__ __align__(256) int    g_bsums[128];
__device__ int g_barc[8];   // one-shot barrier counters (zero-init; reset by k_agg<false>)

// ---------------- software grid barrier ----------------
__device__ __forceinline__ void gbar(int j) {
    __syncthreads();
    if (threadIdx.x == 0) {
        __threadfence();
        atomicAdd(&g_barc[j], 1);
        volatile int* p = &g_barc[j];
        while (*p < CSR_B) { }
        __threadfence();
    }
    __syncthreads();
}

// ---------------- fused CSR build ----------------
__global__ __launch_bounds__(CSR_T) void k_csr(const int* __restrict__ row,
                                               const int* __restrict__ col) {
    const int tid = threadIdx.x, bid = blockIdx.x;
    const int gt = bid * CSR_T + tid;
    const int gstride = CSR_B * CSR_T;

    for (int i = gt; i < NN; i += gstride) g_deg[i] = 0;
    gbar(0);

    for (int e = gt; e < NE; e += gstride) atomicAdd(&g_deg[col[e]], 1);
    gbar(1);

    int excl = 0;
    int valid = 0;
    if (bid < SCAN_NBLK) {
        int i = bid * CSR_T + tid;
        valid = (i < NN);
        int v = valid ? __ldcg(&g_deg[i]) : 0;
        if (valid) g_dinv[i] = rsqrtf((float)v + 1.0f);   // +1 self-loop
        int lane = tid & 31, wid = tid >> 5;
        int x = v;
        #pragma unroll
        for (int d = 1; d < 32; d <<= 1) {
            int y = __shfl_up_sync(0xffffffffu, x, d);
            if (lane >= d) x += y;
        }
        __shared__ int wsum[32];
        if (lane == 31) wsum[wid] = x;
        __syncthreads();
        if (wid == 0) {
            int s = wsum[lane];
            int sx = s;
            #pragma unroll
            for (int d = 1; d < 32; d <<= 1) {
                int y = __shfl_up_sync(0xffffffffu, sx, d);
                if (lane >= d) sx += y;
            }
            wsum[lane] = sx - s;
        }
        __syncthreads();
        int incl = x + wsum[wid];
        excl = incl - v;
        if (tid == 1023) g_bsums[bid] = incl;
    }
    gbar(2);

    {
        __shared__ int ws[4];
        int v = 0, incl = 0;
        if (bid == 0) {
            if (tid < 128) {
                v = (tid < SCAN_NBLK) ? __ldcg(&g_bsums[tid]) : 0;
                int lane = tid & 31, wid = tid >> 5;
                int x = v;
                #pragma unroll
                for (int d = 1; d < 32; d <<= 1) {
                    int y = __shfl_up_sync(0xffffffffu, x, d);
                    if (lane >= d) x += y;
                }
                if (lane == 31) ws[wid] = x;
                incl = x;
            }
            __syncthreads();
            if (tid < 128) {
                int wid = tid >> 5;
                int off = 0;
                for (int w = 0; w < wid; w++) off += ws[w];
                incl += off;
                if (tid < SCAN_NBLK) g_bsums[tid] = incl - v;
            }
        }
    }
    gbar(3);

    if (bid < SCAN_NBLK && valid) {
        int i = bid * CSR_T + tid;
        int rp = excl + __ldcg(&g_bsums[bid]);
        g_rowptr[i] = rp;
        g_cursor[i] = rp;
    }
    if (bid == 0 && tid == 0) g_rowptr[NN] = NE;
    gbar(4);

    // fill: payload is just src (dinv folded into gemm epilogue premultiply)
    for (int e = gt; e < NE; e += gstride) {
        int c = col[e];
        int p = atomicAdd(&g_cursor[c], 1);
        g_src[p] = row[e];
    }
}

// ---------------- tensor-core GEMM (smem-staged A, premultiplied output) ----------------
// g_h0h[r,64](fp16) = dinv[r] * (A[r,:] @ W[:,64])
// 128 threads = 4 warps x 16 rows = 64 rows/block. A staged via wide coalesced loads.
__device__ __forceinline__ void mma16816(float d[4], uint32 a0, uint32 a1, uint32 a2,
                                         uint32 a3, uint32 b0, uint32 b1) {
    asm volatile(
        "mma.sync.aligned.m16n8k16.row.col.f32.f16.f16.f32 "
        "{%0,%1,%2,%3}, {%4,%5,%6,%7}, {%8,%9}, {%0,%1,%2,%3};"
        : "+f"(d[0]), "+f"(d[1]), "+f"(d[2]), "+f"(d[3])
        : "r"(a0), "r"(a1), "r"(a2), "r"(a3), "r"(b0), "r"(b1));
}

template <int K, bool A_HALF>
__global__ __launch_bounds__(128) void k_gemm_mma(const float* __restrict__ Af,
                                                  const float* __restrict__ W) {
    __shared__ __half Wt[64][K + 8];     // W transposed [n][k]
    __shared__ __half Ahs[64][K + 8];    // staged A tile (also reused as epilogue staging)

    for (int i = threadIdx.x; i < K * 64; i += 128) {
        int k = i >> 6, n = i & 63;
        Wt[n][k] = __float2half(W[i]);
    }

    const int rbase = blockIdx.x * 64;
    if (A_HALF) {
        const __half* Ah = reinterpret_cast<const __half*>(g_h1h);  // device-side symbol
        const int nvec = 64 * (K / 8);                              // uint4 count
        #pragma unroll
        for (int it = 0; it < nvec / 128; it++) {
            int i = it * 128 + threadIdx.x;
            int r = i / (K / 8), v = i % (K / 8);
            int R = rbase + r;
            uint4 val = make_uint4(0, 0, 0, 0);
            if (R < NN) val = reinterpret_cast<const uint4*>(Ah + (size_t)R * K)[v];
            reinterpret_cast<uint4*>(&Ahs[r][0])[v] = val;
        }
    } else {
        const int nvec = 64 * (K / 4);                              // float4 count
        #pragma unroll
        for (int it = 0; it < nvec / 128; it++) {
            int i = it * 128 + threadIdx.x;
            int r = i / (K / 4), v = i % (K / 4);
            int R = rbase + r;
            float4 f = make_float4(0.f, 0.f, 0.f, 0.f);
            if (R < NN) f = reinterpret_cast<const float4*>(Af + (size_t)R * K)[v];
            __half2 h01 = __floats2half2_rn(f.x, f.y);
            __half2 h23 = __floats2half2_rn(f.z, f.w);
            uint2 pk = make_uint2(*reinterpret_cast<uint32*>(&h01),
                                  *reinterpret_cast<uint32*>(&h23));
            *reinterpret_cast<uint2*>(&Ahs[r][v * 4]) = pk;
        }
    }
    __syncthreads();

    const int warp = threadIdx.x >> 5, lane = threadIdx.x & 31;
    const int gr = lane >> 2;           // 0..7
    const int kc = (lane & 3) * 2;      // 0,2,4,6
    const int lr0 = warp * 16 + gr;     // local rows
    const int lr1 = lr0 + 8;
    const int R0 = rbase + lr0, R1 = rbase + lr1;

    float d[8][4];
    #pragma unroll
    for (int nt = 0; nt < 8; nt++)
        #pragma unroll
        for (int t = 0; t < 4; t++) d[nt][t] = 0.f;

    #pragma unroll
    for (int q = 0; q < K / 16; q++) {
        int k0 = q * 16 + kc;
        uint32 a0 = *reinterpret_cast<const uint32*>(&Ahs[lr0][k0]);
        uint32 a1 = *reinterpret_cast<const uint32*>(&Ahs[lr1][k0]);
        uint32 a2 = *reinterpret_cast<const uint32*>(&Ahs[lr0][k0 + 8]);
        uint32 a3 = *reinterpret_cast<const uint32*>(&Ahs[lr1][k0 + 8]);
        #pragma unroll
        for (int nt = 0; nt < 8; nt++) {
            int n = nt * 8 + gr;
            uint32 b0 = *reinterpret_cast<const uint32*>(&Wt[n][k0]);
            uint32 b1 = *reinterpret_cast<const uint32*>(&Wt[n][k0 + 8]);
            mma16816(d[nt], a0, a1, a2, a3, b0, b1);
        }
    }

    // premultiply by dinv[row], stage into Ahs (own-warp rows only), coalesced store
    float dv0 = (R0 < NN) ? g_dinv[R0] : 0.f;
    float dv1 = (R1 < NN) ? g_dinv[R1] : 0.f;
    #pragma unroll
    for (int nt = 0; nt < 8; nt++) {
        int c = nt * 8 + kc;
        *reinterpret_cast<__half2*>(&Ahs[lr0][c]) =
            __floats2half2_rn(d[nt][0] * dv0, d[nt][1] * dv0);
        *reinterpret_cast<__half2*>(&Ahs[lr1][c]) =
            __floats2half2_rn(d[nt][2] * dv1, d[nt][3] * dv1);
    }
    __syncwarp();
    __half* outp = reinterpret_cast<__half*>(g_h0h);
    #pragma unroll
    for (int rr = 0; rr < 16; rr++) {
        int R = rbase + warp * 16 + rr;
        if (R < NN) {
            uint32 v = reinterpret_cast<const uint32*>(&Ahs[warp * 16 + rr][0])[lane];
            reinterpret_cast<uint32*>(outp + (size_t)R * 64)[lane] = v;
        }
    }
}

// ---------------- GCN aggregate: h[c] = relu(dinv[c]*(pre[c] + sum pre[src]) + b) ----------------
template <bool FUSE_HEAD>
__global__ __launch_bounds__(256) void k_agg(const float* __restrict__ bias,
                                             const float* __restrict__ Wl,
                                             const float* __restrict__ bl) {
    // agg1 runs strictly after k_csr -> safe place to reset grid-barrier counters
    if (!FUSE_HEAD && blockIdx.x == 0 && threadIdx.x == 0) {
        #pragma unroll
        for (int j = 0; j < 8; j++) g_barc[j] = 0;
    }
    __shared__ float Wls[16 * 68];
    __shared__ float hs[8][64];
    __shared__ float blc[8];
    if (FUSE_HEAD) {
        for (int i = threadIdx.x; i < 16 * 64; i += 256) {
            int o = i & 15, k = i >> 4;
            int sel = o >> 3, oo = o & 7;
            Wls[o * 68 + k] = Wl[(sel * 64 + k) * 8 + oo];
        }
        if (threadIdx.x < 8) blc[threadIdx.x] = bl[threadIdx.x];
        __syncthreads();
    }

    int gw = (blockIdx.x * 256 + threadIdx.x) >> 5;   // grid exact: 12500 blocks
    int lane = threadIdx.x & 31;
    int w = threadIdx.x >> 5;
    float di = g_dinv[gw];
    int beg = g_rowptr[gw], end = g_rowptr[gw + 1];

    const __half2* hin = g_h0h;
    float2 hself = __half22float2(hin[(size_t)gw * 32 + lane]);  // pre[c]
    float ax = hself.x, ay = hself.y;

    int e = beg;
    for (; e + 4 <= end; e += 4) {
        int s0 = __ldg(&g_src[e]);
        int s1 = __ldg(&g_src[e + 1]);
        int s2 = __ldg(&g_src[e + 2]);
        int s3 = __ldg(&g_src[e + 3]);
        float2 v0 = __half22float2(__ldg(&hin[(size_t)s0 * 32 + lane]));
        float2 v1 = __half22float2(__ldg(&hin[(size_t)s1 * 32 + lane]));
        float2 v2 = __half22float2(__ldg(&hin[(size_t)s2 * 32 + lane]));
        float2 v3 = __half22float2(__ldg(&hin[(size_t)s3 * 32 + lane]));
        ax += v0.x + v1.x + v2.x + v3.x;
        ay += v0.y + v1.y + v2.y + v3.y;
    }
    for (; e < end; e++) {
        int s = __ldg(&g_src[e]);
        float2 v = __half22float2(__ldg(&hin[(size_t)s * 32 + lane]));
        ax += v.x;
        ay += v.y;
    }
    float2 b = reinterpret_cast<const float2*>(bias)[lane];
    float rx = fmaxf(fmaf(di, ax, b.x), 0.f);
    float ry = fmaxf(fmaf(di, ay, b.y), 0.f);

    if (!FUSE_HEAD) {
        g_h1h[(size_t)gw * 32 + lane] = __floats2half2_rn(rx, ry);  // unscaled h1
    } else {
        hs[w][2 * lane + 0] = rx;
        hs[w][2 * lane + 1] = ry;
        __syncwarp();
        if (lane < 16) {
            float acc = (lane < 8) ? blc[lane] : 0.f;
            const float4* h4 = reinterpret_cast<const float4*>(hs[w]);
            const float4* w4 = reinterpret_cast<const float4*>(Wls + lane * 68);
            #pragma unroll
            for (int k4 = 0; k4 < 16; k4++) {
                float4 hv = h4[k4];
                float4 wv = w4[k4];
                acc += hv.x * wv.x + hv.y * wv.y + hv.z * wv.z + hv.w * wv.w;
            }
            g_y[(size_t)gw * 16 + lane] = acc;
        }
        __syncwarp();
    }
}

// ---------------- edge phase: out[e] = y[row][0:8] + y[col][8:16] ----------------
__global__ void k_edge(const int* __restrict__ row, const int* __restrict__ col,
                       float* __restrict__ out) {
    int idx = blockIdx.x * 256 + threadIdx.x;
    if (idx >= NE * 2) return;
    int e = idx >> 1, c = idx & 1;
    int r = row[e], cl = col[e];
    const float4* y4 = reinterpret_cast<const float4*>(g_y);
    float4 a = y4[(size_t)r * 4 + c];
    float4 b = y4[(size_t)cl * 4 + 2 + c];
    float4 o;
    o.x = a.x + b.x; o.y = a.y + b.y; o.z = a.z + b.z; o.w = a.w + b.w;
    reinterpret_cast<float4*>(out)[idx] = o;
}

// ---------------- launch ----------------
extern "C" void kernel_launch(void* const* d_in, const int* in_sizes, int n_in,
                              void* d_out, int out_size) {
    const float* x  = (const float*)d_in[0];
    const int*   ei = (const int*)  d_in[1];
    const float* W1 = (const float*)d_in[2];
    const float* b1 = (const float*)d_in[3];
    const float* W2 = (const float*)d_in[4];
    const float* b2 = (const float*)d_in[5];
    const float* Wl = (const float*)d_in[6];
    const float* bl = (const float*)d_in[7];
    float* out = (float*)d_out;

    const int* row = ei;        // edge_index[0]
    const int* col = ei + NE;   // edge_index[1]

    const int GEMM_G = (NN + 63) / 64;   // 1563 blocks (64 rows each)

    // CSR build first (gemm epilogue needs dinv)
    k_csr<<<CSR_B, CSR_T>>>(row, col);

    // conv1: pre = dinv * (x@W1) ; h1 = relu(dinv*(pre_self+sum)+b1)
    k_gemm_mma<FIN, false><<<GEMM_G, 128>>>(x, W1);
    k_agg<false><<<(NN * 32) / 256, 256>>>(b1, Wl, bl);

    // conv2 + fused edge head
    k_gemm_mma<HID, true><<<GEMM_G, 128>>>(nullptr, W2);
    k_agg<true><<<(NN * 32) / 256, 256>>>(b2, Wl, bl);

    // per-edge sum
    k_edge<<<(NE * 2 + 255) / 256, 256>>>(row, col, out);
}